// round 11
// baseline (speedup 1.0000x reference)
#include <cuda_runtime.h>
#include <cuda_fp16.h>
#include <math.h>
#include <stdint.h>

// Problem constants
#define Bv 8
#define Sv 4096
#define Ev 512
#define Hv 8
#define Dv 64
#define Mv (Bv * Sv)          // 32768 rows
#define EPSv 1e-6f

// GEMM tiling: 128(M) x 128(N) tiles, K-chunk 64 (fp16), K=512 -> 8 chunks
#define TILE_BYTES 16384              // 128 rows x 64 fp16 (128B rows, swizzled)
#define STAGE_BYTES (3 * TILE_BYTES)  // Ahi, Alo, Bhi
#define NCHUNK 8
#define SMEM_GEMM (3 * STAGE_BYTES + 1024)   // 3 stages = 148480 B

// ---------------------------------------------------------------------------
// Scratch (device globals: allocation-free rule)
// ---------------------------------------------------------------------------
__device__ float g_q[(size_t)Mv * Ev];
__device__ float g_k[(size_t)Mv * Ev];
__device__ float g_v[(size_t)Mv * Ev];
__device__ float g_kv[Bv * Hv * Dv * Dv];
__device__ float g_ksum[Bv * Hv * Dv];

// Packed SW128-swizzled fp16 tiles: [mtile(256)][kchunk(8)][16384B]
__device__ __align__(1024) unsigned char g_xt_hi[(size_t)Mv * Ev * 2];
__device__ __align__(1024) unsigned char g_xt_lo[(size_t)Mv * Ev * 2];
__device__ __align__(1024) unsigned char g_at_hi[(size_t)Mv * Ev * 2];
__device__ __align__(1024) unsigned char g_at_lo[(size_t)Mv * Ev * 2];
// Weights (hi only, fp16), transposed+packed: [w(4)][ntile(4)][kchunk(8)][16384B]
__device__ __align__(1024) unsigned char g_w_hi[4][(size_t)Ev * Ev * 2];

// ---------------------------------------------------------------------------
// Helpers (baseline PTX only)
// ---------------------------------------------------------------------------
__device__ __forceinline__ uint32_t smem_u32(const void* p) {
    uint32_t a;
    asm("{ .reg .u64 t; cvta.to.shared.u64 t, %1; cvt.u32.u64 %0, t; }"
        : "=r"(a) : "l"(p));
    return a;
}

__device__ __forceinline__ void cp16(uint32_t dst, const void* src) {
    asm volatile("cp.async.cg.shared.global [%0], [%1], 16;"
                 :: "r"(dst), "l"(src) : "memory");
}
#define CP_COMMIT() asm volatile("cp.async.commit_group;" ::: "memory")
#define CP_WAIT2()  asm volatile("cp.async.wait_group 2;" ::: "memory")
#define CP_WAIT1()  asm volatile("cp.async.wait_group 1;" ::: "memory")
#define CP_WAIT0()  asm volatile("cp.async.wait_group 0;" ::: "memory")

__device__ __forceinline__ void ldsm_x4(uint32_t* r, uint32_t addr) {
    asm volatile("ldmatrix.sync.aligned.m8n8.x4.shared.b16 {%0,%1,%2,%3}, [%4];"
                 : "=r"(r[0]), "=r"(r[1]), "=r"(r[2]), "=r"(r[3]) : "r"(addr));
}

// D += A(f16) * B(f16), m16n8k16, A row-major, B col-major, f32 accum
__device__ __forceinline__ void mma16816(float* d, const uint32_t* a, const uint32_t* b) {
    asm volatile(
        "mma.sync.aligned.m16n8k16.row.col.f32.f16.f16.f32 "
        "{%0,%1,%2,%3}, {%4,%5,%6,%7}, {%8,%9}, {%0,%1,%2,%3};"
        : "+f"(d[0]), "+f"(d[1]), "+f"(d[2]), "+f"(d[3])
        : "r"(a[0]), "r"(a[1]), "r"(a[2]), "r"(a[3]), "r"(b[0]), "r"(b[1]));
}

__device__ __forceinline__ uint32_t sw128(uint32_t off) {
    return off ^ ((off >> 3) & 0x70);
}
__device__ __forceinline__ uint32_t pack_h2(__half a, __half b) {
    return (uint32_t)__half_as_ushort(a) | ((uint32_t)__half_as_ushort(b) << 16);
}

// ---------------------------------------------------------------------------
// Kernel 0: zero the accumulators (graph replays)
// ---------------------------------------------------------------------------
__global__ void zero_acc_kernel() {
    int i = blockIdx.x * blockDim.x + threadIdx.x;
    if (i < Bv * Hv * Dv * Dv) g_kv[i] = 0.0f;
    if (i < Bv * Hv * Dv)      g_ksum[i] = 0.0f;
}

// ---------------------------------------------------------------------------
// packA: fp32 [M,512] row-major -> SW128-swizzled fp16 hi/lo tiles
// ---------------------------------------------------------------------------
__global__ __launch_bounds__(256)
void packA_kernel(const float* __restrict__ X,
                  unsigned char* __restrict__ hiT, unsigned char* __restrict__ loT)
{
    __shared__ unsigned char sh[TILE_BYTES];
    __shared__ unsigned char sl[TILE_BYTES];
    const int tid = threadIdx.x;
    const int kc = blockIdx.x, mt = blockIdx.y;
    const int kt = kc * 64;
    const size_t mbase = (size_t)mt * 128;
#pragma unroll
    for (int i = 0; i < 8; i++) {
        int slot = tid + i * 256;            // 0..2047
        int r  = slot >> 4;                  // 0..127
        int c4 = (slot & 15) << 2;           // 0..60
        float4 xv = *(const float4*)(X + (mbase + r) * Ev + kt + c4);
        float xa[4] = {xv.x, xv.y, xv.z, xv.w};
        __half h[4], l[4];
#pragma unroll
        for (int j = 0; j < 4; j++) {
            h[j] = __float2half(xa[j]);
            l[j] = __float2half(xa[j] - __half2float(h[j]));
        }
        uint32_t sw = sw128((uint32_t)(r * 128 + c4 * 2));
        uint2 hv = {pack_h2(h[0], h[1]), pack_h2(h[2], h[3])};
        uint2 lv = {pack_h2(l[0], l[1]), pack_h2(l[2], l[3])};
        *(uint2*)(sh + sw) = hv;
        *(uint2*)(sl + sw) = lv;
    }
    __syncthreads();
    size_t toff = ((size_t)mt * NCHUNK + kc) * TILE_BYTES;
#pragma unroll
    for (int i = 0; i < 4; i++) {
        int slot = tid + i * 256;
        *(uint4*)(hiT + toff + slot * 16) = *(uint4*)(sh + slot * 16);
        *(uint4*)(loT + toff + slot * 16) = *(uint4*)(sl + slot * 16);
    }
}

// ---------------------------------------------------------------------------
// packB: W [K=512][N=512] fp32 -> transposed swizzled fp16 tiles (hi only)
// stored as B[n][k] with k contiguous (col-major B for mma.row.col)
// ---------------------------------------------------------------------------
__global__ __launch_bounds__(256)
void packB_kernel(const float* __restrict__ W, unsigned char* __restrict__ hiT)
{
    __shared__ unsigned char sh[TILE_BYTES];
    const int tid = threadIdx.x;
    const int kc = blockIdx.x, nt = blockIdx.y;
    const int kt = kc * 64, n0 = nt * 128;
#pragma unroll
    for (int i = 0; i < 8; i++) {
        int slot = tid + i * 256;            // 0..2047
        int r  = slot >> 5;                  // 0..63  (k within chunk)
        int c4 = (slot & 31) << 2;           // 0..124 (n within tile)
        float4 wv = *(const float4*)(W + (size_t)(kt + r) * Ev + n0 + c4);
        float wa[4] = {wv.x, wv.y, wv.z, wv.w};
#pragma unroll
        for (int j = 0; j < 4; j++) {
            uint32_t sw = sw128((uint32_t)((c4 + j) * 128 + r * 2));
            *(unsigned short*)(sh + sw) = __half_as_ushort(__float2half(wa[j]));
        }
    }
    __syncthreads();
    size_t toff = ((size_t)nt * NCHUNK + kc) * TILE_BYTES;
#pragma unroll
    for (int i = 0; i < 4; i++) {
        int slot = tid + i * 256;
        *(uint4*)(hiT + toff + slot * 16) = *(uint4*)(sh + slot * 16);
    }
}

// ---------------------------------------------------------------------------
// GEMM core: 2-term fp16 split (Ah*Bh + Al*Bh), fp32 accumulation.
// 256 threads = 8 warps (4 along m, 2 along n); warp tile 32x64.
// 3-stage cp.async pipeline (48KB/stage).
// ---------------------------------------------------------------------------
__device__ __forceinline__ void copy_stage(uint32_t sdst,
    const unsigned char* ah, const unsigned char* al,
    const unsigned char* bh, int tid)
{
#pragma unroll
    for (int i = 0; i < 4; i++) {
        int off = (tid + i * 256) * 16;
        cp16(sdst + off,                  ah + off);
        cp16(sdst + TILE_BYTES + off,     al + off);
        cp16(sdst + 2 * TILE_BYTES + off, bh + off);
    }
    CP_COMMIT();
}

__device__ __forceinline__ void gemm_mainloop(
    uint32_t sb, const unsigned char* ah, const unsigned char* al,
    const unsigned char* bh, int tid, int lane, int wm, int wn,
    float acc[2][8][4])
{
    // Prologue: prefetch chunks 0,1,2
    copy_stage(sb,                   ah, al, bh, tid);
    copy_stage(sb + STAGE_BYTES,     ah + TILE_BYTES, al + TILE_BYTES, bh + TILE_BYTES, tid);
    copy_stage(sb + 2 * STAGE_BYTES, ah + 2 * TILE_BYTES, al + 2 * TILE_BYTES,
               bh + 2 * TILE_BYTES, tid);

    const int a_row  = wm * 32 + (lane & 7) + ((lane >> 3) & 1) * 8;  // + mf*16
    const int a_colb = ((lane >> 4) & 1) * 16;                        // + ks*32
    const int b_row  = wn * 64 + (lane & 7) + ((lane >> 4) & 1) * 8;  // + nfp*16
    const int b_colb = ((lane >> 3) & 1) * 16;                        // + ks*32

    for (int t = 0; t < NCHUNK; t++) {
        if (t < NCHUNK - 2)      { CP_WAIT2(); }
        else if (t == NCHUNK - 2){ CP_WAIT1(); }
        else                     { CP_WAIT0(); }
        __syncthreads();
        const uint32_t st = sb + (uint32_t)(t % 3) * STAGE_BYTES;

#pragma unroll
        for (int ks = 0; ks < 4; ks++) {
            uint32_t ahf[2][4], alf[2][4];
#pragma unroll
            for (int mf = 0; mf < 2; mf++) {
                uint32_t off = sw128((uint32_t)((a_row + mf * 16) * 128 + a_colb + ks * 32));
                ldsm_x4(ahf[mf], st + off);
                ldsm_x4(alf[mf], st + TILE_BYTES + off);
            }
#pragma unroll
            for (int nfp = 0; nfp < 4; nfp++) {
                uint32_t off = sw128((uint32_t)((b_row + nfp * 16) * 128 + b_colb + ks * 32));
                uint32_t bh4[4];
                ldsm_x4(bh4, st + 2 * TILE_BYTES + off);
                const int ne = nfp * 2, no = nfp * 2 + 1;
                // term 1: Ah*Bh
                mma16816(acc[0][ne], ahf[0], bh4);   mma16816(acc[0][no], ahf[0], bh4 + 2);
                mma16816(acc[1][ne], ahf[1], bh4);   mma16816(acc[1][no], ahf[1], bh4 + 2);
                // term 2: Al*Bh
                mma16816(acc[0][ne], alf[0], bh4);   mma16816(acc[0][no], alf[0], bh4 + 2);
                mma16816(acc[1][ne], alf[1], bh4);   mma16816(acc[1][no], alf[1], bh4 + 2);
            }
        }
        __syncthreads();
        if (t + 3 < NCHUNK) {
            size_t coff = (size_t)(t + 3) * TILE_BYTES;
            copy_stage(st, ah + coff, al + coff, bh + coff, tid);
        }
    }
}

__device__ __forceinline__ void gemm_epilogue(
    float acc[2][8][4], const float* __restrict__ bias, float* __restrict__ C,
    int mt, int nt, int lane, int wm, int wn, int act)
{
    const int row_base = mt * 128 + wm * 32 + (lane >> 2);
    const int col_base = nt * 128 + wn * 64 + (lane & 3) * 2;
#pragma unroll
    for (int mf = 0; mf < 2; mf++) {
#pragma unroll
        for (int nf = 0; nf < 8; nf++) {
            int col = col_base + nf * 8;
            float b0 = __ldg(bias + col), b1 = __ldg(bias + col + 1);
#pragma unroll
            for (int half = 0; half < 2; half++) {
                int row = row_base + mf * 16 + half * 8;
                float x0 = acc[mf][nf][half * 2 + 0] + b0;
                float x1 = acc[mf][nf][half * 2 + 1] + b1;
                if (act) {
                    x0 = (x0 > 0.0f) ? (x0 + 1.0f) : expf(x0);
                    x1 = (x1 > 0.0f) ? (x1 + 1.0f) : expf(x1);
                }
                *(float2*)(C + (size_t)row * Ev + col) = make_float2(x0, x1);
            }
        }
    }
}

// Merged Q/K/V projection: grid (12, 256); blockIdx.x = w*4 + nt (x-fastest so
// the 12 consumers of each A m-tile are adjacent -> A read ~once from DRAM).
__global__ __launch_bounds__(256)
void qkv_gemm_kernel(const unsigned char* __restrict__ Ahi,
                     const unsigned char* __restrict__ Alo,
                     const unsigned char* __restrict__ Wh,
                     const float* __restrict__ bq, const float* __restrict__ bk,
                     const float* __restrict__ bv,
                     float* __restrict__ q, float* __restrict__ k, float* __restrict__ v)
{
    extern __shared__ unsigned char smem_raw[];
    const uint32_t sb = (smem_u32(smem_raw) + 1023u) & ~1023u;
    const int tid = threadIdx.x;
    const int lane = tid & 31, wid = tid >> 5;
    const int w  = blockIdx.x >> 2;
    const int nt = blockIdx.x & 3;
    const int mt = blockIdx.y;
    const int wm = wid & 3, wn = wid >> 2;

    const unsigned char* ah = Ahi + (size_t)mt * NCHUNK * TILE_BYTES;
    const unsigned char* al = Alo + (size_t)mt * NCHUNK * TILE_BYTES;
    const unsigned char* bh = Wh + ((size_t)w * 4 + nt) * NCHUNK * TILE_BYTES;

    float acc[2][8][4];
#pragma unroll
    for (int mf = 0; mf < 2; mf++)
#pragma unroll
        for (int nf = 0; nf < 8; nf++)
#pragma unroll
            for (int j = 0; j < 4; j++) acc[mf][nf][j] = 0.0f;

    gemm_mainloop(sb, ah, al, bh, tid, lane, wm, wn, acc);

    const float* bias = (w == 0) ? bq : (w == 1) ? bk : bv;
    float* C          = (w == 0) ? q  : (w == 1) ? k  : v;
    gemm_epilogue(acc, bias, C, mt, nt, lane, wm, wn, (w < 2) ? 1 : 0);
}

// Output projection: grid (4, 256)
__global__ __launch_bounds__(256)
void out_gemm_kernel(const unsigned char* __restrict__ Ahi,
                     const unsigned char* __restrict__ Alo,
                     const unsigned char* __restrict__ Wh,
                     const float* __restrict__ bias, float* __restrict__ C)
{
    extern __shared__ unsigned char smem_raw[];
    const uint32_t sb = (smem_u32(smem_raw) + 1023u) & ~1023u;
    const int tid = threadIdx.x;
    const int lane = tid & 31, wid = tid >> 5;
    const int nt = blockIdx.x;
    const int mt = blockIdx.y;
    const int wm = wid & 3, wn = wid >> 2;

    const unsigned char* ah = Ahi + (size_t)mt * NCHUNK * TILE_BYTES;
    const unsigned char* al = Alo + (size_t)mt * NCHUNK * TILE_BYTES;
    const unsigned char* bh = Wh + (size_t)nt * NCHUNK * TILE_BYTES;

    float acc[2][8][4];
#pragma unroll
    for (int mf = 0; mf < 2; mf++)
#pragma unroll
        for (int nf = 0; nf < 8; nf++)
#pragma unroll
            for (int j = 0; j < 4; j++) acc[mf][nf][j] = 0.0f;

    gemm_mainloop(sb, ah, al, bh, tid, lane, wm, wn, acc);
    gemm_epilogue(acc, bias, C, mt, nt, lane, wm, wn, 0);
}

// ---------------------------------------------------------------------------
// kvsum: per (b,h) KV = sum_s k (outer) v, ksum = sum_s k
// ---------------------------------------------------------------------------
__global__ __launch_bounds__(256)
void kvsum_kernel() {
    __shared__ float ks[32][64];
    __shared__ float vs[32][64];

    const int tid   = threadIdx.x;
    const int split = blockIdx.x;
    const int bh    = blockIdx.y;
    const int b = bh >> 3, h = bh & 7;
    const int ty = tid >> 4, tx = tid & 15;

    float acc[4][4];
    float ksa[4];
#pragma unroll
    for (int u = 0; u < 4; u++) {
        ksa[u] = 0.0f;
#pragma unroll
        for (int w = 0; w < 4; w++) acc[u][w] = 0.0f;
    }

    const int s_base = split * (Sv / 8);
    for (int chunk = 0; chunk < 16; chunk++) {
        int s0 = s_base + chunk * 32;
#pragma unroll
        for (int s = 0; s < 2; s++) {
            int slot = tid + s * 256;
            int r  = slot >> 4;
            int c4 = (slot & 15) * 4;
            size_t gidx = ((size_t)(b * Sv + s0 + r) * Hv + h) * Dv + c4;
            *(float4*)&ks[r][c4] = *(const float4*)(g_k + gidx);
            *(float4*)&vs[r][c4] = *(const float4*)(g_v + gidx);
        }
        __syncthreads();

        for (int sp = 0; sp < 32; sp++) {
            float kr[4], vr[4];
#pragma unroll
            for (int u = 0; u < 4; u++) kr[u] = ks[sp][ty + 16 * u];
#pragma unroll
            for (int u = 0; u < 4; u++) vr[u] = vs[sp][tx + 16 * u];
#pragma unroll
            for (int u = 0; u < 4; u++)
#pragma unroll
                for (int w = 0; w < 4; w++)
                    acc[u][w] = fmaf(kr[u], vr[w], acc[u][w]);
            if (tx == 0) {
#pragma unroll
                for (int u = 0; u < 4; u++) ksa[u] += kr[u];
            }
        }
        __syncthreads();
    }

#pragma unroll
    for (int u = 0; u < 4; u++)
#pragma unroll
        for (int w = 0; w < 4; w++)
            atomicAdd(&g_kv[(size_t)bh * Dv * Dv + (ty + 16 * u) * Dv + (tx + 16 * w)],
                      acc[u][w]);
    if (tx == 0) {
#pragma unroll
        for (int u = 0; u < 4; u++)
            atomicAdd(&g_ksum[bh * Dv + ty + 16 * u], ksa[u]);
    }
}

// ---------------------------------------------------------------------------
// attn apply: out = (q @ KV) * z, written DIRECTLY as packed fp16 hi/lo tiles
// ---------------------------------------------------------------------------
__global__ __launch_bounds__(256)
void attn_kernel() {
    __shared__ float qs[128][64];
    __shared__ float kvs[64][64];

    const int tid = threadIdx.x;
    const int bh  = blockIdx.x;
    const int b = bh >> 3, h = bh & 7;
    const int st = blockIdx.y;
    const int s0 = st * 128;

#pragma unroll
    for (int s = 0; s < 4; s++) {
        int slot = tid + s * 256;
        *(float4*)((float*)kvs + slot * 4) =
            *(const float4*)(g_kv + (size_t)bh * Dv * Dv + slot * 4);
    }
#pragma unroll
    for (int s = 0; s < 8; s++) {
        int slot = tid + s * 256;
        int r  = slot >> 4;
        int c4 = (slot & 15) * 4;
        *(float4*)&qs[r][c4] =
            *(const float4*)(g_q + ((size_t)(b * Sv + s0 + r) * Hv + h) * Dv + c4);
    }
    __syncthreads();

    const int ty = tid >> 4, tx = tid & 15;
    const int m0 = ty * 8, n0 = tx * 4;

    float acc[8][4];
    float zacc[8];
#pragma unroll
    for (int i = 0; i < 8; i++) {
        zacc[i] = 0.0f;
#pragma unroll
        for (int j = 0; j < 4; j++) acc[i][j] = 0.0f;
    }

    const float* ksp = g_ksum + bh * Dv;
#pragma unroll 4
    for (int k = 0; k < 64; k++) {
        float bfr[4];
        *(float4*)bfr = *(float4*)&kvs[k][n0];
        float ksv = __ldg(ksp + k);
#pragma unroll
        for (int i = 0; i < 8; i++) {
            float a = qs[m0 + i][k];
            zacc[i] = fmaf(a, ksv, zacc[i]);
#pragma unroll
            for (int j = 0; j < 4; j++)
                acc[i][j] = fmaf(a, bfr[j], acc[i][j]);
        }
    }

    // Emit packed swizzled fp16 hi/lo tile (tile = (b*32+st, kchunk h))
    const size_t toff = ((size_t)(b * 32 + st) * NCHUNK + h) * TILE_BYTES;
#pragma unroll
    for (int i = 0; i < 8; i++) {
        float z = 1.0f / (zacc[i] + EPSv);
        __half hb[4], lb[4];
#pragma unroll
        for (int j = 0; j < 4; j++) {
            float o = acc[i][j] * z;
            hb[j] = __float2half(o);
            lb[j] = __float2half(o - __half2float(hb[j]));
        }
        uint32_t sw = sw128((uint32_t)((m0 + i) * 128 + n0 * 2));
        uint2 hv = {pack_h2(hb[0], hb[1]), pack_h2(hb[2], hb[3])};
        uint2 lv = {pack_h2(lb[0], lb[1]), pack_h2(lb[2], lb[3])};
        *(uint2*)(g_at_hi + toff + sw) = hv;
        *(uint2*)(g_at_lo + toff + sw) = lv;
    }
}

// ---------------------------------------------------------------------------
// Launch
// ---------------------------------------------------------------------------
extern "C" void kernel_launch(void* const* d_in, const int* in_sizes, int n_in,
                              void* d_out, int out_size)
{
    const float* x  = (const float*)d_in[0];
    const float* Wq = (const float*)d_in[1];
    const float* bq = (const float*)d_in[2];
    const float* Wk = (const float*)d_in[3];
    const float* bk = (const float*)d_in[4];
    const float* Wv = (const float*)d_in[5];
    const float* bv = (const float*)d_in[6];
    const float* Wo = (const float*)d_in[7];
    const float* bo = (const float*)d_in[8];
    float* out = (float*)d_out;

    float *qp, *kp, *vp;
    unsigned char *xh, *xl, *ath, *atl, *wh;
    cudaGetSymbolAddress((void**)&qp,  g_q);
    cudaGetSymbolAddress((void**)&kp,  g_k);
    cudaGetSymbolAddress((void**)&vp,  g_v);
    cudaGetSymbolAddress((void**)&xh,  g_xt_hi);
    cudaGetSymbolAddress((void**)&xl,  g_xt_lo);
    cudaGetSymbolAddress((void**)&ath, g_at_hi);
    cudaGetSymbolAddress((void**)&atl, g_at_lo);
    cudaGetSymbolAddress((void**)&wh,  g_w_hi);
    const size_t WSZ = (size_t)Ev * Ev * 2;

    cudaFuncSetAttribute(qkv_gemm_kernel, cudaFuncAttributeMaxDynamicSharedMemorySize, SMEM_GEMM);
    cudaFuncSetAttribute(out_gemm_kernel, cudaFuncAttributeMaxDynamicSharedMemorySize, SMEM_GEMM);

    // 0) zero accumulators (graph replays)
    zero_acc_kernel<<<(Bv * Hv * Dv * Dv + 255) / 256, 256>>>();

    // 1) pack inputs: x -> fp16 hi/lo tiles, weights -> fp16 hi tiles
    packA_kernel<<<dim3(NCHUNK, Mv / 128), 256>>>(x, xh, xl);
    packB_kernel<<<dim3(NCHUNK, 4), 256>>>(Wq, wh + 0 * WSZ);
    packB_kernel<<<dim3(NCHUNK, 4), 256>>>(Wk, wh + 1 * WSZ);
    packB_kernel<<<dim3(NCHUNK, 4), 256>>>(Wv, wh + 2 * WSZ);
    packB_kernel<<<dim3(NCHUNK, 4), 256>>>(Wo, wh + 3 * WSZ);

    // 2) merged q/k/v projections (feature map fused into q,k epilogues)
    qkv_gemm_kernel<<<dim3(12, Mv / 128), 256, SMEM_GEMM>>>(
        xh, xl, wh, bq, bk, bv, qp, kp, vp);

    // 3) KV outer-product reduction + ksum
    kvsum_kernel<<<dim3(8, Bv * Hv), 256>>>();

    // 4) attention apply -> packed fp16 hi/lo tiles
    attn_kernel<<<dim3(Bv * Hv, Sv / 128), 256>>>();

    // 5) output projection -> d_out
    out_gemm_kernel<<<dim3(4, Mv / 128), 256, SMEM_GEMM>>>(
        ath, atl, wh + 3 * WSZ, bo, out);
}

// round 13
// speedup vs baseline: 1.7585x; 1.7585x over previous
#include <cuda_runtime.h>
#include <cuda_fp16.h>
#include <math.h>
#include <stdint.h>

// Problem constants
#define Bv 8
#define Sv 4096
#define Ev 512
#define Hv 8
#define Dv 64
#define Mv (Bv * Sv)          // 32768 rows
#define EPSv 1e-6f

// GEMM tiling: 128(M) x 128(N) tiles, K-chunk 64 (fp16), K=512 -> 8 chunks
#define TILE_BYTES 16384              // 128 rows x 64 fp16 (128B rows, swizzled)
#define STAGE_BYTES (3 * TILE_BYTES)  // Ahi, Alo, Bhi = 48KB
#define NCHUNK 8
#define SMEM_GEMM (2 * STAGE_BYTES + 1024)   // 2 stages = 99328 B -> 2 CTAs/SM

// ---------------------------------------------------------------------------
// Scratch (device globals: allocation-free rule)
// ---------------------------------------------------------------------------
__device__ float g_q[(size_t)Mv * Ev];
__device__ float g_k[(size_t)Mv * Ev];
__device__ float g_v[(size_t)Mv * Ev];
__device__ float g_kv[Bv * Hv * Dv * Dv];
__device__ float g_ksum[Bv * Hv * Dv];

// Packed SW128-swizzled fp16 tiles: [mtile(256)][kchunk(8)][16384B]
__device__ __align__(1024) unsigned char g_xt_hi[(size_t)Mv * Ev * 2];
__device__ __align__(1024) unsigned char g_xt_lo[(size_t)Mv * Ev * 2];
__device__ __align__(1024) unsigned char g_at_hi[(size_t)Mv * Ev * 2];
__device__ __align__(1024) unsigned char g_at_lo[(size_t)Mv * Ev * 2];
// Weights (hi only, fp16), transposed+packed: [w(4)][ntile(4)][kchunk(8)][16384B]
__device__ __align__(1024) unsigned char g_w_hi[4][(size_t)Ev * Ev * 2];

// ---------------------------------------------------------------------------
// Helpers (baseline PTX only)
// ---------------------------------------------------------------------------
__device__ __forceinline__ uint32_t smem_u32(const void* p) {
    uint32_t a;
    asm("{ .reg .u64 t; cvta.to.shared.u64 t, %1; cvt.u32.u64 %0, t; }"
        : "=r"(a) : "l"(p));
    return a;
}

__device__ __forceinline__ void cp16(uint32_t dst, const void* src) {
    asm volatile("cp.async.cg.shared.global [%0], [%1], 16;"
                 :: "r"(dst), "l"(src) : "memory");
}
#define CP_COMMIT() asm volatile("cp.async.commit_group;" ::: "memory")
#define CP_WAIT1()  asm volatile("cp.async.wait_group 1;" ::: "memory")
#define CP_WAIT0()  asm volatile("cp.async.wait_group 0;" ::: "memory")

__device__ __forceinline__ void ldsm_x4(uint32_t* r, uint32_t addr) {
    asm volatile("ldmatrix.sync.aligned.m8n8.x4.shared.b16 {%0,%1,%2,%3}, [%4];"
                 : "=r"(r[0]), "=r"(r[1]), "=r"(r[2]), "=r"(r[3]) : "r"(addr));
}

// D += A(f16) * B(f16), m16n8k16, A row-major, B col-major, f32 accum
__device__ __forceinline__ void mma16816(float* d, const uint32_t* a, const uint32_t* b) {
    asm volatile(
        "mma.sync.aligned.m16n8k16.row.col.f32.f16.f16.f32 "
        "{%0,%1,%2,%3}, {%4,%5,%6,%7}, {%8,%9}, {%0,%1,%2,%3};"
        : "+f"(d[0]), "+f"(d[1]), "+f"(d[2]), "+f"(d[3])
        : "r"(a[0]), "r"(a[1]), "r"(a[2]), "r"(a[3]), "r"(b[0]), "r"(b[1]));
}

__device__ __forceinline__ uint32_t sw128(uint32_t off) {
    return off ^ ((off >> 3) & 0x70);
}
__device__ __forceinline__ uint32_t pack_h2(__half a, __half b) {
    return (uint32_t)__half_as_ushort(a) | ((uint32_t)__half_as_ushort(b) << 16);
}

// ---------------------------------------------------------------------------
// Kernel 0: zero the accumulators (graph replays)
// ---------------------------------------------------------------------------
__global__ void zero_acc_kernel() {
    int i = blockIdx.x * blockDim.x + threadIdx.x;
    if (i < Bv * Hv * Dv * Dv) g_kv[i] = 0.0f;
    if (i < Bv * Hv * Dv)      g_ksum[i] = 0.0f;
}

// ---------------------------------------------------------------------------
// packA: fp32 [M,512] row-major -> SW128-swizzled fp16 hi/lo tiles
// ---------------------------------------------------------------------------
__global__ __launch_bounds__(256)
void packA_kernel(const float* __restrict__ X,
                  unsigned char* __restrict__ hiT, unsigned char* __restrict__ loT)
{
    __shared__ unsigned char sh[TILE_BYTES];
    __shared__ unsigned char sl[TILE_BYTES];
    const int tid = threadIdx.x;
    const int kc = blockIdx.x, mt = blockIdx.y;
    const int kt = kc * 64;
    const size_t mbase = (size_t)mt * 128;
#pragma unroll
    for (int i = 0; i < 8; i++) {
        int slot = tid + i * 256;            // 0..2047
        int r  = slot >> 4;                  // 0..127
        int c4 = (slot & 15) << 2;           // 0..60
        float4 xv = *(const float4*)(X + (mbase + r) * Ev + kt + c4);
        float xa[4] = {xv.x, xv.y, xv.z, xv.w};
        __half h[4], l[4];
#pragma unroll
        for (int j = 0; j < 4; j++) {
            h[j] = __float2half(xa[j]);
            l[j] = __float2half(xa[j] - __half2float(h[j]));
        }
        uint32_t sw = sw128((uint32_t)(r * 128 + c4 * 2));
        uint2 hv = {pack_h2(h[0], h[1]), pack_h2(h[2], h[3])};
        uint2 lv = {pack_h2(l[0], l[1]), pack_h2(l[2], l[3])};
        *(uint2*)(sh + sw) = hv;
        *(uint2*)(sl + sw) = lv;
    }
    __syncthreads();
    size_t toff = ((size_t)mt * NCHUNK + kc) * TILE_BYTES;
#pragma unroll
    for (int i = 0; i < 4; i++) {
        int slot = tid + i * 256;
        *(uint4*)(hiT + toff + slot * 16) = *(uint4*)(sh + slot * 16);
        *(uint4*)(loT + toff + slot * 16) = *(uint4*)(sl + slot * 16);
    }
}

// ---------------------------------------------------------------------------
// packB (all 4 weights in one launch): W [K,N] fp32 -> transposed swizzled
// fp16 tiles (hi only), B[n][k] k-contiguous. grid (8 kchunk, 4 ntile, 4 w)
// ---------------------------------------------------------------------------
__global__ __launch_bounds__(256)
void packB_all_kernel(const float* __restrict__ W0, const float* __restrict__ W1,
                      const float* __restrict__ W2, const float* __restrict__ W3,
                      unsigned char* __restrict__ hiT)
{
    __shared__ unsigned char sh[TILE_BYTES];
    const int tid = threadIdx.x;
    const int kc = blockIdx.x, nt = blockIdx.y, w = blockIdx.z;
    const float* W = (w == 0) ? W0 : (w == 1) ? W1 : (w == 2) ? W2 : W3;
    const int kt = kc * 64, n0 = nt * 128;
#pragma unroll
    for (int i = 0; i < 8; i++) {
        int slot = tid + i * 256;            // 0..2047
        int r  = slot >> 5;                  // 0..63  (k within chunk)
        int c4 = (slot & 31) << 2;           // 0..124 (n within tile)
        float4 wv = *(const float4*)(W + (size_t)(kt + r) * Ev + n0 + c4);
        float wa[4] = {wv.x, wv.y, wv.z, wv.w};
#pragma unroll
        for (int j = 0; j < 4; j++) {
            uint32_t sw = sw128((uint32_t)((c4 + j) * 128 + r * 2));
            *(unsigned short*)(sh + sw) = __half_as_ushort(__float2half(wa[j]));
        }
    }
    __syncthreads();
    size_t toff = (((size_t)w * 4 + nt) * NCHUNK + kc) * TILE_BYTES;
#pragma unroll
    for (int i = 0; i < 4; i++) {
        int slot = tid + i * 256;
        *(uint4*)(hiT + toff + slot * 16) = *(uint4*)(sh + slot * 16);
    }
}

// ---------------------------------------------------------------------------
// GEMM core: 2-term fp16 split (Ah*Bh + Al*Bh), fp32 accumulation.
// 256 threads = 8 warps (4 along m, 2 along n); warp tile 32x64.
// 2-stage cp.async double buffer (48KB/stage) -> 2 CTAs/SM.
// ---------------------------------------------------------------------------
__device__ __forceinline__ void copy_stage(uint32_t sdst,
    const unsigned char* ah, const unsigned char* al,
    const unsigned char* bh, int tid)
{
#pragma unroll
    for (int i = 0; i < 4; i++) {
        int off = (tid + i * 256) * 16;
        cp16(sdst + off,                  ah + off);
        cp16(sdst + TILE_BYTES + off,     al + off);
        cp16(sdst + 2 * TILE_BYTES + off, bh + off);
    }
    CP_COMMIT();
}

template <int ACT>
__global__ __launch_bounds__(256, 2)
void gemm_mma_kernel(const unsigned char* __restrict__ Ahi,
                     const unsigned char* __restrict__ Alo,
                     const unsigned char* __restrict__ Bh,
                     const float* __restrict__ bias, float* __restrict__ C)
{
    extern __shared__ unsigned char smem_raw[];
    const uint32_t sb = (smem_u32(smem_raw) + 1023u) & ~1023u;
    const int tid  = threadIdx.x;
    const int lane = tid & 31, wid = tid >> 5;
    const int nt = blockIdx.x;   // 0..3
    const int mt = blockIdx.y;   // 0..255
    const int wm = wid & 3;      // m warp: 0..3  (32 rows each)
    const int wn = wid >> 2;     // n warp: 0..1  (64 cols each)

    const unsigned char* ah = Ahi + (size_t)mt * NCHUNK * TILE_BYTES;
    const unsigned char* al = Alo + (size_t)mt * NCHUNK * TILE_BYTES;
    const unsigned char* bh = Bh  + (size_t)nt * NCHUNK * TILE_BYTES;

    // Prologue: prefetch chunks 0, 1
    copy_stage(sb,               ah, al, bh, tid);
    copy_stage(sb + STAGE_BYTES, ah + TILE_BYTES, al + TILE_BYTES, bh + TILE_BYTES, tid);

    float acc[2][8][4];
#pragma unroll
    for (int mf = 0; mf < 2; mf++)
#pragma unroll
        for (int nf = 0; nf < 8; nf++)
#pragma unroll
            for (int j = 0; j < 4; j++) acc[mf][nf][j] = 0.0f;

    const int a_row  = wm * 32 + (lane & 7) + ((lane >> 3) & 1) * 8;  // + mf*16
    const int a_colb = ((lane >> 4) & 1) * 16;                        // + ks*32
    const int b_row  = wn * 64 + (lane & 7) + ((lane >> 4) & 1) * 8;  // + nfp*16
    const int b_colb = ((lane >> 3) & 1) * 16;                        // + ks*32

    for (int t = 0; t < NCHUNK; t++) {
        if (t == NCHUNK - 1) { CP_WAIT0(); } else { CP_WAIT1(); }
        __syncthreads();
        const uint32_t st = sb + (uint32_t)(t & 1) * STAGE_BYTES;

#pragma unroll
        for (int ks = 0; ks < 4; ks++) {
            uint32_t ahf[2][4], alf[2][4];
#pragma unroll
            for (int mf = 0; mf < 2; mf++) {
                uint32_t off = sw128((uint32_t)((a_row + mf * 16) * 128 + a_colb + ks * 32));
                ldsm_x4(ahf[mf], st + off);
                ldsm_x4(alf[mf], st + TILE_BYTES + off);
            }
#pragma unroll
            for (int nfp = 0; nfp < 4; nfp++) {
                uint32_t off = sw128((uint32_t)((b_row + nfp * 16) * 128 + b_colb + ks * 32));
                uint32_t bh4[4];
                ldsm_x4(bh4, st + 2 * TILE_BYTES + off);
                const int ne = nfp * 2, no = nfp * 2 + 1;
                // term 1: Ah*Bh
                mma16816(acc[0][ne], ahf[0], bh4);   mma16816(acc[0][no], ahf[0], bh4 + 2);
                mma16816(acc[1][ne], ahf[1], bh4);   mma16816(acc[1][no], ahf[1], bh4 + 2);
                // term 2: Al*Bh
                mma16816(acc[0][ne], alf[0], bh4);   mma16816(acc[0][no], alf[0], bh4 + 2);
                mma16816(acc[1][ne], alf[1], bh4);   mma16816(acc[1][no], alf[1], bh4 + 2);
            }
        }
        __syncthreads();
        if (t + 2 < NCHUNK) {
            size_t coff = (size_t)(t + 2) * TILE_BYTES;
            copy_stage(st, ah + coff, al + coff, bh + coff, tid);
        }
    }

    // Epilogue
    const int row_base = mt * 128 + wm * 32 + (lane >> 2);
    const int col_base = nt * 128 + wn * 64 + (lane & 3) * 2;
#pragma unroll
    for (int mf = 0; mf < 2; mf++) {
#pragma unroll
        for (int nf = 0; nf < 8; nf++) {
            int col = col_base + nf * 8;
            float b0 = __ldg(bias + col), b1 = __ldg(bias + col + 1);
#pragma unroll
            for (int half = 0; half < 2; half++) {
                int row = row_base + mf * 16 + half * 8;
                float x0 = acc[mf][nf][half * 2 + 0] + b0;
                float x1 = acc[mf][nf][half * 2 + 1] + b1;
                if (ACT) {
                    x0 = (x0 > 0.0f) ? (x0 + 1.0f) : expf(x0);
                    x1 = (x1 > 0.0f) ? (x1 + 1.0f) : expf(x1);
                }
                *(float2*)(C + (size_t)row * Ev + col) = make_float2(x0, x1);
            }
        }
    }
}

// ---------------------------------------------------------------------------
// kvsum: per (b,h) KV = sum_s k (outer) v, ksum = sum_s k
// ---------------------------------------------------------------------------
__global__ __launch_bounds__(256)
void kvsum_kernel() {
    __shared__ float ks[32][64];
    __shared__ float vs[32][64];

    const int tid   = threadIdx.x;
    const int split = blockIdx.x;
    const int bh    = blockIdx.y;
    const int b = bh >> 3, h = bh & 7;
    const int ty = tid >> 4, tx = tid & 15;

    float acc[4][4];
    float ksa[4];
#pragma unroll
    for (int u = 0; u < 4; u++) {
        ksa[u] = 0.0f;
#pragma unroll
        for (int w = 0; w < 4; w++) acc[u][w] = 0.0f;
    }

    const int s_base = split * (Sv / 8);
    for (int chunk = 0; chunk < 16; chunk++) {
        int s0 = s_base + chunk * 32;
#pragma unroll
        for (int s = 0; s < 2; s++) {
            int slot = tid + s * 256;
            int r  = slot >> 4;
            int c4 = (slot & 15) * 4;
            size_t gidx = ((size_t)(b * Sv + s0 + r) * Hv + h) * Dv + c4;
            *(float4*)&ks[r][c4] = *(const float4*)(g_k + gidx);
            *(float4*)&vs[r][c4] = *(const float4*)(g_v + gidx);
        }
        __syncthreads();

        for (int sp = 0; sp < 32; sp++) {
            float kr[4], vr[4];
#pragma unroll
            for (int u = 0; u < 4; u++) kr[u] = ks[sp][ty + 16 * u];
#pragma unroll
            for (int u = 0; u < 4; u++) vr[u] = vs[sp][tx + 16 * u];
#pragma unroll
            for (int u = 0; u < 4; u++)
#pragma unroll
                for (int w = 0; w < 4; w++)
                    acc[u][w] = fmaf(kr[u], vr[w], acc[u][w]);
            if (tx == 0) {
#pragma unroll
                for (int u = 0; u < 4; u++) ksa[u] += kr[u];
            }
        }
        __syncthreads();
    }

#pragma unroll
    for (int u = 0; u < 4; u++)
#pragma unroll
        for (int w = 0; w < 4; w++)
            atomicAdd(&g_kv[(size_t)bh * Dv * Dv + (ty + 16 * u) * Dv + (tx + 16 * w)],
                      acc[u][w]);
    if (tx == 0) {
#pragma unroll
        for (int u = 0; u < 4; u++)
            atomicAdd(&g_ksum[bh * Dv + ty + 16 * u], ksa[u]);
    }
}

// ---------------------------------------------------------------------------
// attn apply: out = (q @ KV) * z, written DIRECTLY as packed fp16 hi/lo tiles
// ---------------------------------------------------------------------------
__global__ __launch_bounds__(256)
void attn_kernel() {
    __shared__ float qs[128][64];
    __shared__ float kvs[64][64];

    const int tid = threadIdx.x;
    const int bh  = blockIdx.x;
    const int b = bh >> 3, h = bh & 7;
    const int st = blockIdx.y;
    const int s0 = st * 128;

#pragma unroll
    for (int s = 0; s < 4; s++) {
        int slot = tid + s * 256;
        *(float4*)((float*)kvs + slot * 4) =
            *(const float4*)(g_kv + (size_t)bh * Dv * Dv + slot * 4);
    }
#pragma unroll
    for (int s = 0; s < 8; s++) {
        int slot = tid + s * 256;
        int r  = slot >> 4;
        int c4 = (slot & 15) * 4;
        *(float4*)&qs[r][c4] =
            *(const float4*)(g_q + ((size_t)(b * Sv + s0 + r) * Hv + h) * Dv + c4);
    }
    __syncthreads();

    const int ty = tid >> 4, tx = tid & 15;
    const int m0 = ty * 8, n0 = tx * 4;

    float acc[8][4];
    float zacc[8];
#pragma unroll
    for (int i = 0; i < 8; i++) {
        zacc[i] = 0.0f;
#pragma unroll
        for (int j = 0; j < 4; j++) acc[i][j] = 0.0f;
    }

    const float* ksp = g_ksum + bh * Dv;
#pragma unroll 4
    for (int k = 0; k < 64; k++) {
        float bfr[4];
        *(float4*)bfr = *(float4*)&kvs[k][n0];
        float ksv = __ldg(ksp + k);
#pragma unroll
        for (int i = 0; i < 8; i++) {
            float a = qs[m0 + i][k];
            zacc[i] = fmaf(a, ksv, zacc[i]);
#pragma unroll
            for (int j = 0; j < 4; j++)
                acc[i][j] = fmaf(a, bfr[j], acc[i][j]);
        }
    }

    // Emit packed swizzled fp16 hi/lo tile (tile = (b*32+st, kchunk h))
    const size_t toff = ((size_t)(b * 32 + st) * NCHUNK + h) * TILE_BYTES;
#pragma unroll
    for (int i = 0; i < 8; i++) {
        float z = 1.0f / (zacc[i] + EPSv);
        __half hb[4], lb[4];
#pragma unroll
        for (int j = 0; j < 4; j++) {
            float o = acc[i][j] * z;
            hb[j] = __float2half(o);
            lb[j] = __float2half(o - __half2float(hb[j]));
        }
        uint32_t sw = sw128((uint32_t)((m0 + i) * 128 + n0 * 2));
        uint2 hv = {pack_h2(hb[0], hb[1]), pack_h2(hb[2], hb[3])};
        uint2 lv = {pack_h2(lb[0], lb[1]), pack_h2(lb[2], lb[3])};
        *(uint2*)(g_at_hi + toff + sw) = hv;
        *(uint2*)(g_at_lo + toff + sw) = lv;
    }
}

// ---------------------------------------------------------------------------
// Launch
// ---------------------------------------------------------------------------
extern "C" void kernel_launch(void* const* d_in, const int* in_sizes, int n_in,
                              void* d_out, int out_size)
{
    const float* x  = (const float*)d_in[0];
    const float* Wq = (const float*)d_in[1];
    const float* bq = (const float*)d_in[2];
    const float* Wk = (const float*)d_in[3];
    const float* bk = (const float*)d_in[4];
    const float* Wv = (const float*)d_in[5];
    const float* bv = (const float*)d_in[6];
    const float* Wo = (const float*)d_in[7];
    const float* bo = (const float*)d_in[8];
    float* out = (float*)d_out;

    float *qp, *kp, *vp;
    unsigned char *xh, *xl, *ath, *atl, *wh;
    cudaGetSymbolAddress((void**)&qp,  g_q);
    cudaGetSymbolAddress((void**)&kp,  g_k);
    cudaGetSymbolAddress((void**)&vp,  g_v);
    cudaGetSymbolAddress((void**)&xh,  g_xt_hi);
    cudaGetSymbolAddress((void**)&xl,  g_xt_lo);
    cudaGetSymbolAddress((void**)&ath, g_at_hi);
    cudaGetSymbolAddress((void**)&atl, g_at_lo);
    cudaGetSymbolAddress((void**)&wh,  g_w_hi);
    const size_t WSZ = (size_t)Ev * Ev * 2;

    cudaFuncSetAttribute(gemm_mma_kernel<0>, cudaFuncAttributeMaxDynamicSharedMemorySize, SMEM_GEMM);
    cudaFuncSetAttribute(gemm_mma_kernel<1>, cudaFuncAttributeMaxDynamicSharedMemorySize, SMEM_GEMM);

    // 0) zero accumulators (graph replays)                       [launch 1]
    zero_acc_kernel<<<(Bv * Hv * Dv * Dv + 255) / 256, 256>>>();

    // 1) pack inputs                                             [launches 2,3]
    packA_kernel<<<dim3(NCHUNK, Mv / 128), 256>>>(x, xh, xl);
    packB_all_kernel<<<dim3(NCHUNK, 4, 4), 256>>>(Wq, Wk, Wv, Wo, wh);

    // 2) q/k/v projections (feature map fused into q,k)          [launches 4,5,6]
    //    (launch 6 = v-GEMM sits in the ncu -s 5 -c 1 window)
    dim3 gg(Ev / 128, Mv / 128);   // (4, 256)
    gemm_mma_kernel<1><<<gg, 256, SMEM_GEMM>>>(xh, xl, wh + 0 * WSZ, bq, qp);
    gemm_mma_kernel<1><<<gg, 256, SMEM_GEMM>>>(xh, xl, wh + 1 * WSZ, bk, kp);
    gemm_mma_kernel<0><<<gg, 256, SMEM_GEMM>>>(xh, xl, wh + 2 * WSZ, bv, vp);

    // 3) KV outer-product reduction + ksum                       [launch 7]
    kvsum_kernel<<<dim3(8, Bv * Hv), 256>>>();

    // 4) attention apply -> packed fp16 hi/lo tiles              [launch 8]
    attn_kernel<<<dim3(Bv * Hv, Sv / 128), 256>>>();

    // 5) output projection -> d_out                              [launch 9]
    gemm_mma_kernel<0><<<gg, 256, SMEM_GEMM>>>(ath, atl, wh + 3 * WSZ, bo, out);
}

// round 14
// speedup vs baseline: 2.4074x; 1.3690x over previous
#include <cuda_runtime.h>
#include <cuda_fp16.h>
#include <math.h>
#include <stdint.h>

// Problem constants
#define Bv 8
#define Sv 4096
#define Ev 512
#define Hv 8
#define Dv 64
#define Mv (Bv * Sv)          // 32768 rows
#define EPSv 1e-6f

// GEMM tiling: 128(M) x 128(N) tiles, K-chunk 64 (fp16), K=512 -> 8 chunks
#define TILE_BYTES 16384              // 128 rows x 64 fp16 (128B rows, swizzled)
#define STAGE_BYTES (2 * TILE_BYTES)  // Ah, Bh = 32KB  (1-term fp16)
#define NCHUNK 8
#define SMEM_GEMM (2 * STAGE_BYTES + 1024)   // 2 stages = 66560 B

// ---------------------------------------------------------------------------
// Scratch (device globals: allocation-free rule)
// ---------------------------------------------------------------------------
__device__ float g_q[(size_t)Mv * Ev];
__device__ float g_k[(size_t)Mv * Ev];
__device__ float g_v[(size_t)Mv * Ev];
__device__ float g_kv[Bv * Hv * Dv * Dv];
__device__ float g_ksum[Bv * Hv * Dv];

// Packed SW128-swizzled fp16 tiles: [mtile(256)][kchunk(8)][16384B]
__device__ __align__(1024) unsigned char g_xt_hi[(size_t)Mv * Ev * 2];
__device__ __align__(1024) unsigned char g_at_hi[(size_t)Mv * Ev * 2];
// Weights (fp16), transposed+packed: [w(4)][ntile(4)][kchunk(8)][16384B]
__device__ __align__(1024) unsigned char g_w_hi[4][(size_t)Ev * Ev * 2];

// ---------------------------------------------------------------------------
// Helpers (baseline PTX only)
// ---------------------------------------------------------------------------
__device__ __forceinline__ uint32_t smem_u32(const void* p) {
    uint32_t a;
    asm("{ .reg .u64 t; cvta.to.shared.u64 t, %1; cvt.u32.u64 %0, t; }"
        : "=r"(a) : "l"(p));
    return a;
}

__device__ __forceinline__ void cp16(uint32_t dst, const void* src) {
    asm volatile("cp.async.cg.shared.global [%0], [%1], 16;"
                 :: "r"(dst), "l"(src) : "memory");
}
#define CP_COMMIT() asm volatile("cp.async.commit_group;" ::: "memory")
#define CP_WAIT1()  asm volatile("cp.async.wait_group 1;" ::: "memory")
#define CP_WAIT0()  asm volatile("cp.async.wait_group 0;" ::: "memory")

__device__ __forceinline__ void ldsm_x4(uint32_t* r, uint32_t addr) {
    asm volatile("ldmatrix.sync.aligned.m8n8.x4.shared.b16 {%0,%1,%2,%3}, [%4];"
                 : "=r"(r[0]), "=r"(r[1]), "=r"(r[2]), "=r"(r[3]) : "r"(addr));
}

// D += A(f16) * B(f16), m16n8k16, A row-major, B col-major, f32 accum
__device__ __forceinline__ void mma16816(float* d, const uint32_t* a, const uint32_t* b) {
    asm volatile(
        "mma.sync.aligned.m16n8k16.row.col.f32.f16.f16.f32 "
        "{%0,%1,%2,%3}, {%4,%5,%6,%7}, {%8,%9}, {%0,%1,%2,%3};"
        : "+f"(d[0]), "+f"(d[1]), "+f"(d[2]), "+f"(d[3])
        : "r"(a[0]), "r"(a[1]), "r"(a[2]), "r"(a[3]), "r"(b[0]), "r"(b[1]));
}

__device__ __forceinline__ uint32_t sw128(uint32_t off) {
    return off ^ ((off >> 3) & 0x70);
}
__device__ __forceinline__ uint32_t pack_h2(__half a, __half b) {
    return (uint32_t)__half_as_ushort(a) | ((uint32_t)__half_as_ushort(b) << 16);
}

// ---------------------------------------------------------------------------
// Kernel 0: zero the accumulators (graph replays)
// ---------------------------------------------------------------------------
__global__ void zero_acc_kernel() {
    int i = blockIdx.x * blockDim.x + threadIdx.x;
    if (i < Bv * Hv * Dv * Dv) g_kv[i] = 0.0f;
    if (i < Bv * Hv * Dv)      g_ksum[i] = 0.0f;
}

// ---------------------------------------------------------------------------
// packA: fp32 [M,512] row-major -> SW128-swizzled fp16 tiles (single term)
// ---------------------------------------------------------------------------
__global__ __launch_bounds__(256)
void packA_kernel(const float* __restrict__ X, unsigned char* __restrict__ hiT)
{
    __shared__ unsigned char sh[TILE_BYTES];
    const int tid = threadIdx.x;
    const int kc = blockIdx.x, mt = blockIdx.y;
    const int kt = kc * 64;
    const size_t mbase = (size_t)mt * 128;
#pragma unroll
    for (int i = 0; i < 8; i++) {
        int slot = tid + i * 256;            // 0..2047
        int r  = slot >> 4;                  // 0..127
        int c4 = (slot & 15) << 2;           // 0..60
        float4 xv = *(const float4*)(X + (mbase + r) * Ev + kt + c4);
        uint32_t sw = sw128((uint32_t)(r * 128 + c4 * 2));
        uint2 hv = {pack_h2(__float2half(xv.x), __float2half(xv.y)),
                    pack_h2(__float2half(xv.z), __float2half(xv.w))};
        *(uint2*)(sh + sw) = hv;
    }
    __syncthreads();
    size_t toff = ((size_t)mt * NCHUNK + kc) * TILE_BYTES;
#pragma unroll
    for (int i = 0; i < 4; i++) {
        int slot = tid + i * 256;
        *(uint4*)(hiT + toff + slot * 16) = *(uint4*)(sh + slot * 16);
    }
}

// ---------------------------------------------------------------------------
// packB (all 4 weights in one launch): W [K,N] fp32 -> transposed swizzled
// fp16 tiles, B[n][k] k-contiguous. grid (8 kchunk, 4 ntile, 4 w)
// ---------------------------------------------------------------------------
__global__ __launch_bounds__(256)
void packB_all_kernel(const float* __restrict__ W0, const float* __restrict__ W1,
                      const float* __restrict__ W2, const float* __restrict__ W3,
                      unsigned char* __restrict__ hiT)
{
    __shared__ unsigned char sh[TILE_BYTES];
    const int tid = threadIdx.x;
    const int kc = blockIdx.x, nt = blockIdx.y, w = blockIdx.z;
    const float* W = (w == 0) ? W0 : (w == 1) ? W1 : (w == 2) ? W2 : W3;
    const int kt = kc * 64, n0 = nt * 128;
#pragma unroll
    for (int i = 0; i < 8; i++) {
        int slot = tid + i * 256;            // 0..2047
        int r  = slot >> 5;                  // 0..63  (k within chunk)
        int c4 = (slot & 31) << 2;           // 0..124 (n within tile)
        float4 wv = *(const float4*)(W + (size_t)(kt + r) * Ev + n0 + c4);
        float wa[4] = {wv.x, wv.y, wv.z, wv.w};
#pragma unroll
        for (int j = 0; j < 4; j++) {
            uint32_t sw = sw128((uint32_t)((c4 + j) * 128 + r * 2));
            *(unsigned short*)(sh + sw) = __half_as_ushort(__float2half(wa[j]));
        }
    }
    __syncthreads();
    size_t toff = (((size_t)w * 4 + nt) * NCHUNK + kc) * TILE_BYTES;
#pragma unroll
    for (int i = 0; i < 4; i++) {
        int slot = tid + i * 256;
        *(uint4*)(hiT + toff + slot * 16) = *(uint4*)(sh + slot * 16);
    }
}

// ---------------------------------------------------------------------------
// GEMM core: single-term fp16 (A*B), fp32 accumulation.
// 256 threads = 8 warps (4 along m, 2 along n); warp tile 32x64.
// 2-stage cp.async double buffer (32KB/stage).
// ---------------------------------------------------------------------------
__device__ __forceinline__ void copy_stage(uint32_t sdst,
    const unsigned char* ah, const unsigned char* bh, int tid)
{
#pragma unroll
    for (int i = 0; i < 4; i++) {
        int off = (tid + i * 256) * 16;
        cp16(sdst + off,              ah + off);
        cp16(sdst + TILE_BYTES + off, bh + off);
    }
    CP_COMMIT();
}

template <int ACT>
__global__ __launch_bounds__(256, 2)
void gemm_mma_kernel(const unsigned char* __restrict__ Ahi,
                     const unsigned char* __restrict__ Bh,
                     const float* __restrict__ bias, float* __restrict__ C)
{
    extern __shared__ unsigned char smem_raw[];
    const uint32_t sb = (smem_u32(smem_raw) + 1023u) & ~1023u;
    const int tid  = threadIdx.x;
    const int lane = tid & 31, wid = tid >> 5;
    const int nt = blockIdx.x;   // 0..3
    const int mt = blockIdx.y;   // 0..255
    const int wm = wid & 3;      // m warp: 0..3  (32 rows each)
    const int wn = wid >> 2;     // n warp: 0..1  (64 cols each)

    const unsigned char* ah = Ahi + (size_t)mt * NCHUNK * TILE_BYTES;
    const unsigned char* bh = Bh  + (size_t)nt * NCHUNK * TILE_BYTES;

    // Prologue: prefetch chunks 0, 1
    copy_stage(sb,               ah, bh, tid);
    copy_stage(sb + STAGE_BYTES, ah + TILE_BYTES, bh + TILE_BYTES, tid);

    float acc[2][8][4];
#pragma unroll
    for (int mf = 0; mf < 2; mf++)
#pragma unroll
        for (int nf = 0; nf < 8; nf++)
#pragma unroll
            for (int j = 0; j < 4; j++) acc[mf][nf][j] = 0.0f;

    const int a_row  = wm * 32 + (lane & 7) + ((lane >> 3) & 1) * 8;  // + mf*16
    const int a_colb = ((lane >> 4) & 1) * 16;                        // + ks*32
    const int b_row  = wn * 64 + (lane & 7) + ((lane >> 4) & 1) * 8;  // + nfp*16
    const int b_colb = ((lane >> 3) & 1) * 16;                        // + ks*32

    for (int t = 0; t < NCHUNK; t++) {
        if (t == NCHUNK - 1) { CP_WAIT0(); } else { CP_WAIT1(); }
        __syncthreads();
        const uint32_t st = sb + (uint32_t)(t & 1) * STAGE_BYTES;

#pragma unroll
        for (int ks = 0; ks < 4; ks++) {
            uint32_t ahf[2][4];
#pragma unroll
            for (int mf = 0; mf < 2; mf++) {
                uint32_t off = sw128((uint32_t)((a_row + mf * 16) * 128 + a_colb + ks * 32));
                ldsm_x4(ahf[mf], st + off);
            }
#pragma unroll
            for (int nfp = 0; nfp < 4; nfp++) {
                uint32_t off = sw128((uint32_t)((b_row + nfp * 16) * 128 + b_colb + ks * 32));
                uint32_t bh4[4];
                ldsm_x4(bh4, st + TILE_BYTES + off);
                const int ne = nfp * 2, no = nfp * 2 + 1;
                mma16816(acc[0][ne], ahf[0], bh4);   mma16816(acc[0][no], ahf[0], bh4 + 2);
                mma16816(acc[1][ne], ahf[1], bh4);   mma16816(acc[1][no], ahf[1], bh4 + 2);
            }
        }
        __syncthreads();
        if (t + 2 < NCHUNK) {
            size_t coff = (size_t)(t + 2) * TILE_BYTES;
            copy_stage(st, ah + coff, bh + coff, tid);
        }
    }

    // Epilogue
    const int row_base = mt * 128 + wm * 32 + (lane >> 2);
    const int col_base = nt * 128 + wn * 64 + (lane & 3) * 2;
#pragma unroll
    for (int mf = 0; mf < 2; mf++) {
#pragma unroll
        for (int nf = 0; nf < 8; nf++) {
            int col = col_base + nf * 8;
            float b0 = __ldg(bias + col), b1 = __ldg(bias + col + 1);
#pragma unroll
            for (int half = 0; half < 2; half++) {
                int row = row_base + mf * 16 + half * 8;
                float x0 = acc[mf][nf][half * 2 + 0] + b0;
                float x1 = acc[mf][nf][half * 2 + 1] + b1;
                if (ACT) {
                    x0 = (x0 > 0.0f) ? (x0 + 1.0f) : expf(x0);
                    x1 = (x1 > 0.0f) ? (x1 + 1.0f) : expf(x1);
                }
                *(float2*)(C + (size_t)row * Ev + col) = make_float2(x0, x1);
            }
        }
    }
}

// ---------------------------------------------------------------------------
// kvsum: per (b,h) KV = sum_s k (outer) v, ksum = sum_s k  (unchanged)
// ---------------------------------------------------------------------------
__global__ __launch_bounds__(256)
void kvsum_kernel() {
    __shared__ float ks[32][64];
    __shared__ float vs[32][64];

    const int tid   = threadIdx.x;
    const int split = blockIdx.x;
    const int bh    = blockIdx.y;
    const int b = bh >> 3, h = bh & 7;
    const int ty = tid >> 4, tx = tid & 15;

    float acc[4][4];
    float ksa[4];
#pragma unroll
    for (int u = 0; u < 4; u++) {
        ksa[u] = 0.0f;
#pragma unroll
        for (int w = 0; w < 4; w++) acc[u][w] = 0.0f;
    }

    const int s_base = split * (Sv / 8);
    for (int chunk = 0; chunk < 16; chunk++) {
        int s0 = s_base + chunk * 32;
#pragma unroll
        for (int s = 0; s < 2; s++) {
            int slot = tid + s * 256;
            int r  = slot >> 4;
            int c4 = (slot & 15) * 4;
            size_t gidx = ((size_t)(b * Sv + s0 + r) * Hv + h) * Dv + c4;
            *(float4*)&ks[r][c4] = *(const float4*)(g_k + gidx);
            *(float4*)&vs[r][c4] = *(const float4*)(g_v + gidx);
        }
        __syncthreads();

        for (int sp = 0; sp < 32; sp++) {
            float kr[4], vr[4];
#pragma unroll
            for (int u = 0; u < 4; u++) kr[u] = ks[sp][ty + 16 * u];
#pragma unroll
            for (int u = 0; u < 4; u++) vr[u] = vs[sp][tx + 16 * u];
#pragma unroll
            for (int u = 0; u < 4; u++)
#pragma unroll
                for (int w = 0; w < 4; w++)
                    acc[u][w] = fmaf(kr[u], vr[w], acc[u][w]);
            if (tx == 0) {
#pragma unroll
                for (int u = 0; u < 4; u++) ksa[u] += kr[u];
            }
        }
        __syncthreads();
    }

#pragma unroll
    for (int u = 0; u < 4; u++)
#pragma unroll
        for (int w = 0; w < 4; w++)
            atomicAdd(&g_kv[(size_t)bh * Dv * Dv + (ty + 16 * u) * Dv + (tx + 16 * w)],
                      acc[u][w]);
    if (tx == 0) {
#pragma unroll
        for (int u = 0; u < 4; u++)
            atomicAdd(&g_ksum[bh * Dv + ty + 16 * u], ksa[u]);
    }
}

// ---------------------------------------------------------------------------
// attn apply: out = (q @ KV) * z, written DIRECTLY as packed fp16 tiles
// ---------------------------------------------------------------------------
__global__ __launch_bounds__(256)
void attn_kernel() {
    __shared__ float qs[128][64];
    __shared__ float kvs[64][64];

    const int tid = threadIdx.x;
    const int bh  = blockIdx.x;
    const int b = bh >> 3, h = bh & 7;
    const int st = blockIdx.y;
    const int s0 = st * 128;

#pragma unroll
    for (int s = 0; s < 4; s++) {
        int slot = tid + s * 256;
        *(float4*)((float*)kvs + slot * 4) =
            *(const float4*)(g_kv + (size_t)bh * Dv * Dv + slot * 4);
    }
#pragma unroll
    for (int s = 0; s < 8; s++) {
        int slot = tid + s * 256;
        int r  = slot >> 4;
        int c4 = (slot & 15) * 4;
        *(float4*)&qs[r][c4] =
            *(const float4*)(g_q + ((size_t)(b * Sv + s0 + r) * Hv + h) * Dv + c4);
    }
    __syncthreads();

    const int ty = tid >> 4, tx = tid & 15;
    const int m0 = ty * 8, n0 = tx * 4;

    float acc[8][4];
    float zacc[8];
#pragma unroll
    for (int i = 0; i < 8; i++) {
        zacc[i] = 0.0f;
#pragma unroll
        for (int j = 0; j < 4; j++) acc[i][j] = 0.0f;
    }

    const float* ksp = g_ksum + bh * Dv;
#pragma unroll 4
    for (int k = 0; k < 64; k++) {
        float bfr[4];
        *(float4*)bfr = *(float4*)&kvs[k][n0];
        float ksv = __ldg(ksp + k);
#pragma unroll
        for (int i = 0; i < 8; i++) {
            float a = qs[m0 + i][k];
            zacc[i] = fmaf(a, ksv, zacc[i]);
#pragma unroll
            for (int j = 0; j < 4; j++)
                acc[i][j] = fmaf(a, bfr[j], acc[i][j]);
        }
    }

    // Emit packed swizzled fp16 tile (tile = (b*32+st, kchunk h))
    const size_t toff = ((size_t)(b * 32 + st) * NCHUNK + h) * TILE_BYTES;
#pragma unroll
    for (int i = 0; i < 8; i++) {
        float z = 1.0f / (zacc[i] + EPSv);
        uint32_t sw = sw128((uint32_t)((m0 + i) * 128 + n0 * 2));
        uint2 hv = {pack_h2(__float2half(acc[i][0] * z), __float2half(acc[i][1] * z)),
                    pack_h2(__float2half(acc[i][2] * z), __float2half(acc[i][3] * z))};
        *(uint2*)(g_at_hi + toff + sw) = hv;
    }
}

// ---------------------------------------------------------------------------
// Launch
// ---------------------------------------------------------------------------
extern "C" void kernel_launch(void* const* d_in, const int* in_sizes, int n_in,
                              void* d_out, int out_size)
{
    const float* x  = (const float*)d_in[0];
    const float* Wq = (const float*)d_in[1];
    const float* bq = (const float*)d_in[2];
    const float* Wk = (const float*)d_in[3];
    const float* bk = (const float*)d_in[4];
    const float* Wv = (const float*)d_in[5];
    const float* bv = (const float*)d_in[6];
    const float* Wo = (const float*)d_in[7];
    const float* bo = (const float*)d_in[8];
    float* out = (float*)d_out;

    float *qp, *kp, *vp;
    unsigned char *xh, *ath, *wh;
    cudaGetSymbolAddress((void**)&qp,  g_q);
    cudaGetSymbolAddress((void**)&kp,  g_k);
    cudaGetSymbolAddress((void**)&vp,  g_v);
    cudaGetSymbolAddress((void**)&xh,  g_xt_hi);
    cudaGetSymbolAddress((void**)&ath, g_at_hi);
    cudaGetSymbolAddress((void**)&wh,  g_w_hi);
    const size_t WSZ = (size_t)Ev * Ev * 2;

    cudaFuncSetAttribute(gemm_mma_kernel<0>, cudaFuncAttributeMaxDynamicSharedMemorySize, SMEM_GEMM);
    cudaFuncSetAttribute(gemm_mma_kernel<1>, cudaFuncAttributeMaxDynamicSharedMemorySize, SMEM_GEMM);

    // 0) zero accumulators (graph replays)                       [launch 1]
    zero_acc_kernel<<<(Bv * Hv * Dv * Dv + 255) / 256, 256>>>();

    // 1) pack inputs                                             [launches 2,3]
    packA_kernel<<<dim3(NCHUNK, Mv / 128), 256>>>(x, xh);
    packB_all_kernel<<<dim3(NCHUNK, 4, 4), 256>>>(Wq, Wk, Wv, Wo, wh);

    // 2) q/k/v projections (feature map fused into q,k)          [launches 4,5,6]
    dim3 gg(Ev / 128, Mv / 128);   // (4, 256)
    gemm_mma_kernel<1><<<gg, 256, SMEM_GEMM>>>(xh, wh + 0 * WSZ, bq, qp);
    gemm_mma_kernel<1><<<gg, 256, SMEM_GEMM>>>(xh, wh + 1 * WSZ, bk, kp);
    gemm_mma_kernel<0><<<gg, 256, SMEM_GEMM>>>(xh, wh + 2 * WSZ, bv, vp);

    // 3) KV outer-product reduction + ksum                       [launch 7]
    kvsum_kernel<<<dim3(8, Bv * Hv), 256>>>();

    // 4) attention apply -> packed fp16 tiles                    [launch 8]
    attn_kernel<<<dim3(Bv * Hv, Sv / 128), 256>>>();

    // 5) output projection -> d_out                              [launch 9]
    gemm_mma_kernel<0><<<gg, 256, SMEM_GEMM>>>(ath, wh + 3 * WSZ, bo, out);
}

// round 15
// speedup vs baseline: 2.4713x; 1.0266x over previous
#include <cuda_runtime.h>
#include <cuda_fp16.h>
#include <math.h>
#include <stdint.h>

// Problem constants
#define Bv 8
#define Sv 4096
#define Ev 512
#define Hv 8
#define Dv 64
#define Mv (Bv * Sv)          // 32768 rows
#define EPSv 1e-6f

// GEMM tiling: 128(M) x 128(N) tiles, K-chunk 64 (fp16), K=512 -> 8 chunks
#define TILE_BYTES 16384              // 128 rows x 64 fp16 (128B rows, swizzled)
#define STAGE_BYTES (2 * TILE_BYTES)  // Ah, Bh = 32KB
#define NCHUNK 8
#define SMEM_GEMM (2 * STAGE_BYTES + 1024)   // 2 stages = 66560 B

// ---------------------------------------------------------------------------
// Scratch (device globals: allocation-free rule)
// ---------------------------------------------------------------------------
__device__ float g_q[(size_t)Mv * Ev];            // q stays fp32 (attn consumes)
__device__ __half g_kh[(size_t)Mv * Ev];          // k as fp16 (kvsum-only)
__device__ __half g_vh[(size_t)Mv * Ev];          // v as fp16 (kvsum-only)
__device__ float g_kv[Bv * Hv * Dv * Dv];
__device__ float g_ksum[Bv * Hv * Dv];

// Packed SW128-swizzled fp16 tiles: [mtile(256)][kchunk(8)][16384B]
__device__ __align__(1024) unsigned char g_xt_hi[(size_t)Mv * Ev * 2];
__device__ __align__(1024) unsigned char g_at_hi[(size_t)Mv * Ev * 2];
// Weights (fp16), transposed+packed: [w(4)][ntile(4)][kchunk(8)][16384B]
__device__ __align__(1024) unsigned char g_w_hi[4][(size_t)Ev * Ev * 2];

// ---------------------------------------------------------------------------
// Helpers (baseline PTX only)
// ---------------------------------------------------------------------------
__device__ __forceinline__ uint32_t smem_u32(const void* p) {
    uint32_t a;
    asm("{ .reg .u64 t; cvta.to.shared.u64 t, %1; cvt.u32.u64 %0, t; }"
        : "=r"(a) : "l"(p));
    return a;
}

__device__ __forceinline__ void cp16(uint32_t dst, const void* src) {
    asm volatile("cp.async.cg.shared.global [%0], [%1], 16;"
                 :: "r"(dst), "l"(src) : "memory");
}
#define CP_COMMIT() asm volatile("cp.async.commit_group;" ::: "memory")
#define CP_WAIT1()  asm volatile("cp.async.wait_group 1;" ::: "memory")
#define CP_WAIT0()  asm volatile("cp.async.wait_group 0;" ::: "memory")

__device__ __forceinline__ void ldsm_x4(uint32_t* r, uint32_t addr) {
    asm volatile("ldmatrix.sync.aligned.m8n8.x4.shared.b16 {%0,%1,%2,%3}, [%4];"
                 : "=r"(r[0]), "=r"(r[1]), "=r"(r[2]), "=r"(r[3]) : "r"(addr));
}

// D += A(f16) * B(f16), m16n8k16, A row-major, B col-major, f32 accum
__device__ __forceinline__ void mma16816(float* d, const uint32_t* a, const uint32_t* b) {
    asm volatile(
        "mma.sync.aligned.m16n8k16.row.col.f32.f16.f16.f32 "
        "{%0,%1,%2,%3}, {%4,%5,%6,%7}, {%8,%9}, {%0,%1,%2,%3};"
        : "+f"(d[0]), "+f"(d[1]), "+f"(d[2]), "+f"(d[3])
        : "r"(a[0]), "r"(a[1]), "r"(a[2]), "r"(a[3]), "r"(b[0]), "r"(b[1]));
}

__device__ __forceinline__ uint32_t sw128(uint32_t off) {
    return off ^ ((off >> 3) & 0x70);
}
__device__ __forceinline__ uint32_t pack_h2(__half a, __half b) {
    return (uint32_t)__half_as_ushort(a) | ((uint32_t)__half_as_ushort(b) << 16);
}

// ---------------------------------------------------------------------------
// Kernel 0: zero the accumulators (graph replays)
// ---------------------------------------------------------------------------
__global__ void zero_acc_kernel() {
    int i = blockIdx.x * blockDim.x + threadIdx.x;
    if (i < Bv * Hv * Dv * Dv) g_kv[i] = 0.0f;
    if (i < Bv * Hv * Dv)      g_ksum[i] = 0.0f;
}

// ---------------------------------------------------------------------------
// packA: fp32 [M,512] row-major -> SW128-swizzled fp16 tiles
// ---------------------------------------------------------------------------
__global__ __launch_bounds__(256)
void packA_kernel(const float* __restrict__ X, unsigned char* __restrict__ hiT)
{
    __shared__ unsigned char sh[TILE_BYTES];
    const int tid = threadIdx.x;
    const int kc = blockIdx.x, mt = blockIdx.y;
    const int kt = kc * 64;
    const size_t mbase = (size_t)mt * 128;
#pragma unroll
    for (int i = 0; i < 8; i++) {
        int slot = tid + i * 256;            // 0..2047
        int r  = slot >> 4;                  // 0..127
        int c4 = (slot & 15) << 2;           // 0..60
        float4 xv = *(const float4*)(X + (mbase + r) * Ev + kt + c4);
        uint32_t sw = sw128((uint32_t)(r * 128 + c4 * 2));
        uint2 hv = {pack_h2(__float2half(xv.x), __float2half(xv.y)),
                    pack_h2(__float2half(xv.z), __float2half(xv.w))};
        *(uint2*)(sh + sw) = hv;
    }
    __syncthreads();
    size_t toff = ((size_t)mt * NCHUNK + kc) * TILE_BYTES;
#pragma unroll
    for (int i = 0; i < 4; i++) {
        int slot = tid + i * 256;
        *(uint4*)(hiT + toff + slot * 16) = *(uint4*)(sh + slot * 16);
    }
}

// ---------------------------------------------------------------------------
// packB (all 4 weights): W [K,N] fp32 -> transposed swizzled fp16 tiles
// grid (8 kchunk, 4 ntile, 4 w)
// ---------------------------------------------------------------------------
__global__ __launch_bounds__(256)
void packB_all_kernel(const float* __restrict__ W0, const float* __restrict__ W1,
                      const float* __restrict__ W2, const float* __restrict__ W3,
                      unsigned char* __restrict__ hiT)
{
    __shared__ unsigned char sh[TILE_BYTES];
    const int tid = threadIdx.x;
    const int kc = blockIdx.x, nt = blockIdx.y, w = blockIdx.z;
    const float* W = (w == 0) ? W0 : (w == 1) ? W1 : (w == 2) ? W2 : W3;
    const int kt = kc * 64, n0 = nt * 128;
#pragma unroll
    for (int i = 0; i < 8; i++) {
        int slot = tid + i * 256;            // 0..2047
        int r  = slot >> 5;                  // 0..63  (k within chunk)
        int c4 = (slot & 31) << 2;           // 0..124 (n within tile)
        float4 wv = *(const float4*)(W + (size_t)(kt + r) * Ev + n0 + c4);
        float wa[4] = {wv.x, wv.y, wv.z, wv.w};
#pragma unroll
        for (int j = 0; j < 4; j++) {
            uint32_t sw = sw128((uint32_t)((c4 + j) * 128 + r * 2));
            *(unsigned short*)(sh + sw) = __half_as_ushort(__float2half(wa[j]));
        }
    }
    __syncthreads();
    size_t toff = (((size_t)w * 4 + nt) * NCHUNK + kc) * TILE_BYTES;
#pragma unroll
    for (int i = 0; i < 4; i++) {
        int slot = tid + i * 256;
        *(uint4*)(hiT + toff + slot * 16) = *(uint4*)(sh + slot * 16);
    }
}

// ---------------------------------------------------------------------------
// GEMM core: single-term fp16 (A*B), fp32 accumulation.
// 256 threads = 8 warps (4 along m, 2 along n); warp tile 32x64.
// 2-stage cp.async double buffer. Per ks-step: batch all 6 ldsm, then 16 MMA.
// Swizzled addresses hoisted; ks advance is a single XOR (disjoint bit fields).
// HOUT=1 -> write __half2, else float2.
// ---------------------------------------------------------------------------
__device__ __forceinline__ void copy_stage(uint32_t sdst,
    const unsigned char* ah, const unsigned char* bh, int tid)
{
#pragma unroll
    for (int i = 0; i < 4; i++) {
        int off = (tid + i * 256) * 16;
        cp16(sdst + off,              ah + off);
        cp16(sdst + TILE_BYTES + off, bh + off);
    }
    CP_COMMIT();
}

template <int ACT, int HOUT>
__global__ __launch_bounds__(256, 2)
void gemm_mma_kernel(const unsigned char* __restrict__ Ahi,
                     const unsigned char* __restrict__ Bh,
                     const float* __restrict__ bias, void* __restrict__ Cv)
{
    extern __shared__ unsigned char smem_raw[];
    const uint32_t sb = (smem_u32(smem_raw) + 1023u) & ~1023u;
    const int tid  = threadIdx.x;
    const int lane = tid & 31, wid = tid >> 5;
    const int nt = blockIdx.x;   // 0..3
    const int mt = blockIdx.y;   // 0..255
    const int wm = wid & 3;      // m warp: 0..3  (32 rows each)
    const int wn = wid >> 2;     // n warp: 0..1  (64 cols each)

    const unsigned char* ah = Ahi + (size_t)mt * NCHUNK * TILE_BYTES;
    const unsigned char* bh = Bh  + (size_t)nt * NCHUNK * TILE_BYTES;

    // Prologue: prefetch chunks 0, 1
    copy_stage(sb,               ah, bh, tid);
    copy_stage(sb + STAGE_BYTES, ah + TILE_BYTES, bh + TILE_BYTES, tid);

    float acc[2][8][4];
#pragma unroll
    for (int mf = 0; mf < 2; mf++)
#pragma unroll
        for (int nf = 0; nf < 8; nf++)
#pragma unroll
            for (int j = 0; j < 4; j++) acc[mf][nf][j] = 0.0f;

    const int a_row  = wm * 32 + (lane & 7) + ((lane >> 3) & 1) * 8;  // + mf*16
    const int a_colb = ((lane >> 4) & 1) * 16;                        // + ks*32
    const int b_row  = wn * 64 + (lane & 7) + ((lane >> 4) & 1) * 8;  // + nfp*16
    const int b_colb = ((lane >> 3) & 1) * 16;                        // + ks*32

    // Hoisted swizzled offsets for ks=0; ks advance = XOR with ks*32
    // (valid: swizzle XOR bits come only from the row; ks*32 occupies bits 5-6,
    //  disjoint from the col-base bit 4)
    uint32_t aoff[2], boff[4];
#pragma unroll
    for (int mf = 0; mf < 2; mf++)
        aoff[mf] = sw128((uint32_t)((a_row + mf * 16) * 128 + a_colb));
#pragma unroll
    for (int nfp = 0; nfp < 4; nfp++)
        boff[nfp] = (uint32_t)TILE_BYTES
                  + sw128((uint32_t)((b_row + nfp * 16) * 128 + b_colb));

    for (int t = 0; t < NCHUNK; t++) {
        if (t == NCHUNK - 1) { CP_WAIT0(); } else { CP_WAIT1(); }
        __syncthreads();
        const uint32_t st = sb + (uint32_t)(t & 1) * STAGE_BYTES;

#pragma unroll
        for (int ks = 0; ks < 4; ks++) {
            const uint32_t kx = (uint32_t)(ks * 32);
            uint32_t ahf[2][4], bfr[4][4];
            // batch ALL loads first (independent), then all MMAs
            ldsm_x4(ahf[0], st + (aoff[0] ^ kx));
            ldsm_x4(ahf[1], st + (aoff[1] ^ kx));
            ldsm_x4(bfr[0], st + (boff[0] ^ kx));
            ldsm_x4(bfr[1], st + (boff[1] ^ kx));
            ldsm_x4(bfr[2], st + (boff[2] ^ kx));
            ldsm_x4(bfr[3], st + (boff[3] ^ kx));
#pragma unroll
            for (int nfp = 0; nfp < 4; nfp++) {
                const int ne = nfp * 2, no = nfp * 2 + 1;
                mma16816(acc[0][ne], ahf[0], bfr[nfp]);
                mma16816(acc[0][no], ahf[0], bfr[nfp] + 2);
                mma16816(acc[1][ne], ahf[1], bfr[nfp]);
                mma16816(acc[1][no], ahf[1], bfr[nfp] + 2);
            }
        }
        __syncthreads();
        if (t + 2 < NCHUNK) {
            size_t coff = (size_t)(t + 2) * TILE_BYTES;
            copy_stage(st, ah + coff, bh + coff, tid);
        }
    }

    // Epilogue
    const int row_base = mt * 128 + wm * 32 + (lane >> 2);
    const int col_base = nt * 128 + wn * 64 + (lane & 3) * 2;
#pragma unroll
    for (int mf = 0; mf < 2; mf++) {
#pragma unroll
        for (int nf = 0; nf < 8; nf++) {
            int col = col_base + nf * 8;
            float b0 = __ldg(bias + col), b1 = __ldg(bias + col + 1);
#pragma unroll
            for (int half = 0; half < 2; half++) {
                int row = row_base + mf * 16 + half * 8;
                float x0 = acc[mf][nf][half * 2 + 0] + b0;
                float x1 = acc[mf][nf][half * 2 + 1] + b1;
                if (ACT) {
                    x0 = (x0 > 0.0f) ? (x0 + 1.0f) : expf(x0);
                    x1 = (x1 > 0.0f) ? (x1 + 1.0f) : expf(x1);
                }
                if (HOUT) {
                    __half* Ch = (__half*)Cv;
                    *(__half2*)(Ch + (size_t)row * Ev + col) =
                        __floats2half2_rn(x0, x1);
                } else {
                    float* Cf = (float*)Cv;
                    *(float2*)(Cf + (size_t)row * Ev + col) = make_float2(x0, x1);
                }
            }
        }
    }
}

// ---------------------------------------------------------------------------
// kvsum: per (b,h) KV = sum_s k (outer) v, ksum = sum_s k.
// fp16 staged tiles; each thread owns a CONSECUTIVE 4x4 tile:
// d = ty*4+u, m = tx*4+w -> 2 x 8B LDS per s-step (was 8 x 4B scattered).
// ---------------------------------------------------------------------------
__global__ __launch_bounds__(256)
void kvsum_kernel() {
    __shared__ __align__(16) __half ks[32][64];   // 4 KB
    __shared__ __align__(16) __half vs[32][64];   // 4 KB

    const int tid   = threadIdx.x;
    const int split = blockIdx.x;
    const int bh    = blockIdx.y;
    const int b = bh >> 3, h = bh & 7;
    const int ty = tid >> 4, tx = tid & 15;

    float acc[4][4];
    float ksa[4];
#pragma unroll
    for (int u = 0; u < 4; u++) {
        ksa[u] = 0.0f;
#pragma unroll
        for (int w = 0; w < 4; w++) acc[u][w] = 0.0f;
    }

    const int s_base = split * (Sv / 8);
    const int lr  = tid >> 3;          // 0..31 (row for the stage load)
    const int lc8 = (tid & 7) * 8;     // 0..56 (8-half column group)

    for (int chunk = 0; chunk < 16; chunk++) {
        int s0 = s_base + chunk * 32;
        {
            size_t gidx = ((size_t)(b * Sv + s0 + lr) * Hv + h) * Dv + lc8;
            *(uint4*)&ks[lr][lc8] = *(const uint4*)(g_kh + gidx);
            *(uint4*)&vs[lr][lc8] = *(const uint4*)(g_vh + gidx);
        }
        __syncthreads();

        for (int sp = 0; sp < 32; sp++) {
            const __half2* kp2 = (const __half2*)&ks[sp][ty * 4];
            const __half2* vp2 = (const __half2*)&vs[sp][tx * 4];
            float2 k01 = __half22float2(kp2[0]);
            float2 k23 = __half22float2(kp2[1]);
            float2 v01 = __half22float2(vp2[0]);
            float2 v23 = __half22float2(vp2[1]);
            float kr[4] = {k01.x, k01.y, k23.x, k23.y};
            float vr[4] = {v01.x, v01.y, v23.x, v23.y};
#pragma unroll
            for (int u = 0; u < 4; u++)
#pragma unroll
                for (int w = 0; w < 4; w++)
                    acc[u][w] = fmaf(kr[u], vr[w], acc[u][w]);
            if (tx == 0) {
#pragma unroll
                for (int u = 0; u < 4; u++) ksa[u] += kr[u];
            }
        }
        __syncthreads();
    }

#pragma unroll
    for (int u = 0; u < 4; u++)
#pragma unroll
        for (int w = 0; w < 4; w++)
            atomicAdd(&g_kv[(size_t)bh * Dv * Dv + (ty * 4 + u) * Dv + (tx * 4 + w)],
                      acc[u][w]);
    if (tx == 0) {
#pragma unroll
        for (int u = 0; u < 4; u++)
            atomicAdd(&g_ksum[bh * Dv + ty * 4 + u], ksa[u]);
    }
}

// ---------------------------------------------------------------------------
// attn apply: out = (q @ KV) * z, written DIRECTLY as packed fp16 tiles
// ---------------------------------------------------------------------------
__global__ __launch_bounds__(256)
void attn_kernel() {
    __shared__ float qs[128][64];
    __shared__ float kvs[64][64];

    const int tid = threadIdx.x;
    const int bh  = blockIdx.x;
    const int b = bh >> 3, h = bh & 7;
    const int st = blockIdx.y;
    const int s0 = st * 128;

#pragma unroll
    for (int s = 0; s < 4; s++) {
        int slot = tid + s * 256;
        *(float4*)((float*)kvs + slot * 4) =
            *(const float4*)(g_kv + (size_t)bh * Dv * Dv + slot * 4);
    }
#pragma unroll
    for (int s = 0; s < 8; s++) {
        int slot = tid + s * 256;
        int r  = slot >> 4;
        int c4 = (slot & 15) * 4;
        *(float4*)&qs[r][c4] =
            *(const float4*)(g_q + ((size_t)(b * Sv + s0 + r) * Hv + h) * Dv + c4);
    }
    __syncthreads();

    const int ty = tid >> 4, tx = tid & 15;
    const int m0 = ty * 8, n0 = tx * 4;

    float acc[8][4];
    float zacc[8];
#pragma unroll
    for (int i = 0; i < 8; i++) {
        zacc[i] = 0.0f;
#pragma unroll
        for (int j = 0; j < 4; j++) acc[i][j] = 0.0f;
    }

    const float* ksp = g_ksum + bh * Dv;
#pragma unroll 4
    for (int k = 0; k < 64; k++) {
        float bfr[4];
        *(float4*)bfr = *(float4*)&kvs[k][n0];
        float ksv = __ldg(ksp + k);
#pragma unroll
        for (int i = 0; i < 8; i++) {
            float a = qs[m0 + i][k];
            zacc[i] = fmaf(a, ksv, zacc[i]);
#pragma unroll
            for (int j = 0; j < 4; j++)
                acc[i][j] = fmaf(a, bfr[j], acc[i][j]);
        }
    }

    // Emit packed swizzled fp16 tile (tile = (b*32+st, kchunk h))
    const size_t toff = ((size_t)(b * 32 + st) * NCHUNK + h) * TILE_BYTES;
#pragma unroll
    for (int i = 0; i < 8; i++) {
        float z = 1.0f / (zacc[i] + EPSv);
        uint32_t sw = sw128((uint32_t)((m0 + i) * 128 + n0 * 2));
        uint2 hv = {pack_h2(__float2half(acc[i][0] * z), __float2half(acc[i][1] * z)),
                    pack_h2(__float2half(acc[i][2] * z), __float2half(acc[i][3] * z))};
        *(uint2*)(g_at_hi + toff + sw) = hv;
    }
}

// ---------------------------------------------------------------------------
// Launch
// ---------------------------------------------------------------------------
extern "C" void kernel_launch(void* const* d_in, const int* in_sizes, int n_in,
                              void* d_out, int out_size)
{
    const float* x  = (const float*)d_in[0];
    const float* Wq = (const float*)d_in[1];
    const float* bq = (const float*)d_in[2];
    const float* Wk = (const float*)d_in[3];
    const float* bk = (const float*)d_in[4];
    const float* Wv = (const float*)d_in[5];
    const float* bv = (const float*)d_in[6];
    const float* Wo = (const float*)d_in[7];
    const float* bo = (const float*)d_in[8];
    float* out = (float*)d_out;

    float *qp;
    __half *khp, *vhp;
    unsigned char *xh, *ath, *wh;
    cudaGetSymbolAddress((void**)&qp,  g_q);
    cudaGetSymbolAddress((void**)&khp, g_kh);
    cudaGetSymbolAddress((void**)&vhp, g_vh);
    cudaGetSymbolAddress((void**)&xh,  g_xt_hi);
    cudaGetSymbolAddress((void**)&ath, g_at_hi);
    cudaGetSymbolAddress((void**)&wh,  g_w_hi);
    const size_t WSZ = (size_t)Ev * Ev * 2;

    cudaFuncSetAttribute((const void*)gemm_mma_kernel<0,0>, cudaFuncAttributeMaxDynamicSharedMemorySize, SMEM_GEMM);
    cudaFuncSetAttribute((const void*)gemm_mma_kernel<0,1>, cudaFuncAttributeMaxDynamicSharedMemorySize, SMEM_GEMM);
    cudaFuncSetAttribute((const void*)gemm_mma_kernel<1,0>, cudaFuncAttributeMaxDynamicSharedMemorySize, SMEM_GEMM);
    cudaFuncSetAttribute((const void*)gemm_mma_kernel<1,1>, cudaFuncAttributeMaxDynamicSharedMemorySize, SMEM_GEMM);

    // 0) zero accumulators (graph replays)                       [launch 1]
    zero_acc_kernel<<<(Bv * Hv * Dv * Dv + 255) / 256, 256>>>();

    // 1) pack inputs                                             [launches 2,3]
    packA_kernel<<<dim3(NCHUNK, Mv / 128), 256>>>(x, xh);
    packB_all_kernel<<<dim3(NCHUNK, 4, 4), 256>>>(Wq, Wk, Wv, Wo, wh);

    // 2) q/k/v projections (feature map fused into q,k)          [launches 4,5,6]
    //    q -> fp32 (attn consumes), k/v -> fp16 (kvsum consumes)
    dim3 gg(Ev / 128, Mv / 128);   // (4, 256)
    gemm_mma_kernel<1,0><<<gg, 256, SMEM_GEMM>>>(xh, wh + 0 * WSZ, bq, qp);
    gemm_mma_kernel<1,1><<<gg, 256, SMEM_GEMM>>>(xh, wh + 1 * WSZ, bk, khp);
    gemm_mma_kernel<0,1><<<gg, 256, SMEM_GEMM>>>(xh, wh + 2 * WSZ, bv, vhp);

    // 3) KV outer-product reduction + ksum                       [launch 7]
    kvsum_kernel<<<dim3(8, Bv * Hv), 256>>>();

    // 4) attention apply -> packed fp16 tiles                    [launch 8]
    attn_kernel<<<dim3(Bv * Hv, Sv / 128), 256>>>();

    // 5) output projection -> d_out                              [launch 9]
    gemm_mma_kernel<0,0><<<gg, 256, SMEM_GEMM>>>(ath, wh + 3 * WSZ, bo, out);
}